// round 11
// baseline (speedup 1.0000x reference)
#include <cuda_runtime.h>
#include <cuda_fp16.h>
#include <cstdint>

#define N_NODES_MAX 100000
#define D_FEAT 128

// Fixed-point packing: one u64 atomic carries both sum and count.
//   low 40 bits:  sum of dist in 2^-20 units
//   high bits:    edge count (+= 1<<40 per edge)
#define FP_SCALE   1048576.0f          // 2^20
#define FP_INV     (1.0f/1048576.0f)
#define CNT_ONE    (1ULL << 40)
#define SUM_MASK   ((1ULL << 40) - 1)

#define EDGE_TPB   1024
#define EDGE_GRID  148                  // 1 CTA/SM (200KB smem => occ=1)
#define SMEM_BYTES (N_NODES_MAX * 2)    // 200,000 B fp16 pos table

// Scratch (static __device__ arrays — no allocation per harness rules)
__device__ float              g_pos[N_NODES_MAX];   // exact fp32 pos (output col 0)
__device__ __half             g_posh[N_NODES_MAX];  // fp16 pos (smem staging source)
__device__ unsigned long long g_acc[N_NODES_MAX];   // packed {cnt, sum_fx}

// Kernel 1: compact pos column + zero accumulators. DRAM row-activation floor.
__global__ void k_init(const float* __restrict__ h, int n_nodes) {
    int i = blockIdx.x * blockDim.x + threadIdx.x;
    if (i < n_nodes) {
        float v = h[(size_t)i * D_FEAT];
        g_pos[i]  = v;
        g_posh[i] = __float2half(v);
        g_acc[i]  = 0ULL;
    }
}

__device__ __forceinline__ int4 ldcs_int4(const int* p) {
    int4 v;
    asm volatile("ld.global.cs.v4.s32 {%0,%1,%2,%3}, [%4];"
                 : "=r"(v.x), "=r"(v.y), "=r"(v.z), "=r"(v.w)
                 : "l"(p));
    return v;
}

__device__ __forceinline__ void edge_accum_s(const __half* __restrict__ s_pos,
                                             int s, int d) {
    float ps = __half2float(s_pos[s]);
    float pd = __half2float(s_pos[d]);
    float dist = fabsf(ps - pd);
    unsigned long long v = __float2ull_rn(dist * FP_SCALE) + CNT_ONE;
    asm volatile("red.global.add.u64 [%0], %1;"
                 :: "l"(&g_acc[d]), "l"(v) : "memory");
}

// Kernel 2: persistent edge scatter with the full fp16 pos table staged in
// shared memory. Gathers hit the smem crossbar (~4cyc/warp random) instead of
// L1tex divergent wavefronts (~32/warp) — the measured 42us bottleneck.
__global__ void __launch_bounds__(EDGE_TPB, 1)
k_edges(const int* __restrict__ src,
        const int* __restrict__ dst,
        int n_edges, int n_nodes) {
    extern __shared__ __half s_pos[];

    // Stage pos table: vectorized 16B copies (n_nodes=100000 = 12500 * 8 halves)
    {
        const uint4* src_v = reinterpret_cast<const uint4*>(g_posh);
        uint4*       dst_v = reinterpret_cast<uint4*>(s_pos);
        int n_vec = n_nodes / 8;
        for (int i = threadIdx.x; i < n_vec; i += blockDim.x)
            dst_v[i] = src_v[i];
        for (int i = n_vec * 8 + threadIdx.x; i < n_nodes; i += blockDim.x)
            s_pos[i] = g_posh[i];
    }
    __syncthreads();

    int n_quads = n_edges >> 2;
    int stride = gridDim.x * blockDim.x;
    for (int q = blockIdx.x * blockDim.x + threadIdx.x; q < n_quads; q += stride) {
        int e0 = q * 4;
        int4 s4 = ldcs_int4(src + e0);
        int4 d4 = ldcs_int4(dst + e0);
        edge_accum_s(s_pos, s4.x, d4.x);
        edge_accum_s(s_pos, s4.y, d4.y);
        edge_accum_s(s_pos, s4.z, d4.z);
        edge_accum_s(s_pos, s4.w, d4.w);
    }
    // tail (n_edges % 4)
    if (blockIdx.x == 0 && threadIdx.x < (n_edges & 3)) {
        int e = (n_quads << 2) + threadIdx.x;
        edge_accum_s(s_pos, src[e], dst[e]);
    }
}

// Kernel 3: finalize (N,2): col0 = exact fp32 pos, col1 = sum/max(cnt,1)
__global__ void k_final(float* __restrict__ out, int n_nodes) {
    int i = blockIdx.x * blockDim.x + threadIdx.x;
    if (i < n_nodes) {
        unsigned long long v = g_acc[i];
        float cnt = (float)(v >> 40);
        float sum = (float)(v & SUM_MASK) * FP_INV;
        float2 r = make_float2(g_pos[i], sum / fmaxf(cnt, 1.0f));
        *reinterpret_cast<float2*>(out + 2 * (size_t)i) = r;
    }
}

extern "C" void kernel_launch(void* const* d_in, const int* in_sizes, int n_in,
                              void* d_out, int out_size) {
    const float* h   = (const float*)d_in[0];
    const int*   src = (const int*)d_in[1];
    const int*   dst = (const int*)d_in[2];
    float* out = (float*)d_out;

    int n_nodes = in_sizes[0] / D_FEAT;
    int n_edges = in_sizes[1];

    static bool attr_set = false;
    if (!attr_set) {
        cudaFuncSetAttribute(k_edges, cudaFuncAttributeMaxDynamicSharedMemorySize,
                             SMEM_BYTES);
        attr_set = true;
    }

    const int TPB = 256;
    int init_blocks = (n_nodes + TPB - 1) / TPB;
    k_init<<<init_blocks, TPB>>>(h, n_nodes);

    k_edges<<<EDGE_GRID, EDGE_TPB, SMEM_BYTES>>>(src, dst, n_edges, n_nodes);

    k_final<<<init_blocks, TPB>>>(out, n_nodes);
}

// round 12
// speedup vs baseline: 1.2157x; 1.2157x over previous
#include <cuda_runtime.h>
#include <cuda_fp16.h>
#include <cstdint>

#define N_NODES_MAX 100000
#define D_FEAT 128

// Fixed-point packing: one u64 atomic carries both sum and count.
//   low 40 bits: sum of dist in 2^-20 units; high bits: count (+1<<40/edge)
#define FP_SCALE   1048576.0f
#define FP_INV     (1.0f/1048576.0f)
#define CNT_ONE    (1ULL << 40)
#define SUM_MASK   ((1ULL << 40) - 1)

#define EDGE_TPB   1024
#define EDGE_GRID  148
#define SMEM_BYTES (N_NODES_MAX * 2)   // 200,000 B fp16 pos table (fits 227KB)

// Scratch (static __device__ arrays — no allocation per harness rules)
__device__ float                       g_pos[N_NODES_MAX];
__device__ __align__(16) __half        g_posh[N_NODES_MAX];  // 100000 % 8 == 0
__device__ unsigned long long          g_acc[N_NODES_MAX];

// Kernel 1: compact pos column + zero accumulators (DRAM row-activation floor).
__global__ void k_init(const float* __restrict__ h, int n_nodes) {
    int i = blockIdx.x * blockDim.x + threadIdx.x;
    if (i < n_nodes) {
        float v = h[(size_t)i * D_FEAT];
        g_pos[i]  = v;
        g_posh[i] = __float2half(v);
        g_acc[i]  = 0ULL;
    }
}

__device__ __forceinline__ void edge_accum_s(const __half* __restrict__ s_pos,
                                             int s, int d) {
    float ps = __half2float(s_pos[s]);
    float pd = __half2float(s_pos[d]);
    float dist = fabsf(ps - pd);
    unsigned long long v = __float2ull_rn(dist * FP_SCALE) + CNT_ONE;
    asm volatile("red.global.add.u64 [%0], %1;"
                 :: "l"(&g_acc[d]), "l"(v) : "memory");
}

// Kernel 2: persistent edge scatter, full fp16 pos table in smem.
// Software-pipelined: next chunk's 4x int4 index loads are issued BEFORE the
// current chunk's 16 LDS gathers + 8 REDGs, so DRAM latency hides behind work
// even at 32 warps/SM (R10's failure mode).
__global__ void __launch_bounds__(EDGE_TPB, 1)
k_edges(const int* __restrict__ src,
        const int* __restrict__ dst,
        int n_edges, int n_nodes) {
    extern __shared__ __half s_pos[];

    // Stage pos table (16B vector copies; n_nodes % 8 == 0 for this problem,
    // scalar tail otherwise).
    {
        const uint4* sv = reinterpret_cast<const uint4*>(g_posh);
        uint4*       dv = reinterpret_cast<uint4*>(s_pos);
        int n_vec = n_nodes >> 3;
        for (int i = threadIdx.x; i < n_vec; i += EDGE_TPB)
            dv[i] = sv[i];
        for (int i = (n_vec << 3) + threadIdx.x; i < n_nodes; i += EDGE_TPB)
            s_pos[i] = g_posh[i];
    }
    __syncthreads();

    const int stride = EDGE_GRID * EDGE_TPB;       // in 8-edge chunks
    const int n_chunks = n_edges >> 3;
    int c = blockIdx.x * EDGE_TPB + threadIdx.x;

    if (c < n_chunks) {
        const int4* srcv = reinterpret_cast<const int4*>(src);
        const int4* dstv = reinterpret_cast<const int4*>(dst);
        int4 s0 = srcv[c * 2], s1 = srcv[c * 2 + 1];
        int4 d0 = dstv[c * 2], d1 = dstv[c * 2 + 1];
        while (true) {
            int cn = c + stride;
            bool has = cn < n_chunks;
            int4 t0, t1, u0, u1;
            if (has) {                       // prefetch next chunk (MLP=4)
                t0 = srcv[cn * 2]; t1 = srcv[cn * 2 + 1];
                u0 = dstv[cn * 2]; u1 = dstv[cn * 2 + 1];
            }
            edge_accum_s(s_pos, s0.x, d0.x);
            edge_accum_s(s_pos, s0.y, d0.y);
            edge_accum_s(s_pos, s0.z, d0.z);
            edge_accum_s(s_pos, s0.w, d0.w);
            edge_accum_s(s_pos, s1.x, d1.x);
            edge_accum_s(s_pos, s1.y, d1.y);
            edge_accum_s(s_pos, s1.z, d1.z);
            edge_accum_s(s_pos, s1.w, d1.w);
            if (!has) break;
            s0 = t0; s1 = t1; d0 = u0; d1 = u1;
            c = cn;
        }
    }
    // tail (n_edges % 8)
    for (int e = (n_chunks << 3) + blockIdx.x * EDGE_TPB + threadIdx.x;
         e < n_edges; e += stride)
        edge_accum_s(s_pos, src[e], dst[e]);
}

// Kernel 3: finalize (N,2): col0 = exact fp32 pos, col1 = sum/max(cnt,1)
__global__ void k_final(float* __restrict__ out, int n_nodes) {
    int i = blockIdx.x * blockDim.x + threadIdx.x;
    if (i < n_nodes) {
        unsigned long long v = g_acc[i];
        float cnt = (float)(v >> 40);
        float sum = (float)(v & SUM_MASK) * FP_INV;
        float2 r = make_float2(g_pos[i], sum / fmaxf(cnt, 1.0f));
        *reinterpret_cast<float2*>(out + 2 * (size_t)i) = r;
    }
}

extern "C" void kernel_launch(void* const* d_in, const int* in_sizes, int n_in,
                              void* d_out, int out_size) {
    const float* h   = (const float*)d_in[0];
    const int*   src = (const int*)d_in[1];
    const int*   dst = (const int*)d_in[2];
    float* out = (float*)d_out;

    int n_nodes = in_sizes[0] / D_FEAT;
    int n_edges = in_sizes[1];

    static bool attr_set = false;
    if (!attr_set) {
        cudaFuncSetAttribute(k_edges, cudaFuncAttributeMaxDynamicSharedMemorySize,
                             SMEM_BYTES);
        attr_set = true;
    }

    const int TPB = 256;
    int init_blocks = (n_nodes + TPB - 1) / TPB;
    k_init<<<init_blocks, TPB>>>(h, n_nodes);

    k_edges<<<EDGE_GRID, EDGE_TPB, SMEM_BYTES>>>(src, dst, n_edges, n_nodes);

    k_final<<<init_blocks, TPB>>>(out, n_nodes);
}